// round 2
// baseline (speedup 1.0000x reference)
#include <cuda_runtime.h>
#include <cuda_bf16.h>
#include <cstdint>

#define NN   8192
#define FIN  256
#define FOUT 128
#define NC   (NN / 64)   // 128 j-chunks in main kernel

// ---------------- scratch (static device globals; no allocation) ----------------
__device__ float          g_Wh [(size_t)NN * FOUT];
__device__ __align__(16) __nv_bfloat16 g_WhH[(size_t)NN * FOUT];
__device__ __align__(16) __nv_bfloat16 g_WhL[(size_t)NN * FOUT];
__device__ __align__(16) float g_nf1[NN];
__device__ __align__(16) float g_E1 [NN];
__device__ __align__(16) float g_G1 [NN];
__device__ __align__(16) float g_f2 [NN];
__device__ __align__(16) float g_E2 [NN];
__device__ __align__(16) float g_G2 [NN];

__device__ __forceinline__ uint32_t sptr(const void* p) {
    return (uint32_t)__cvta_generic_to_shared(p);
}

// =====================================================================
// Kernel 1: Wh = h @ W  (fp32 SIMT tiled GEMM), also emits bf16 hi/lo split
// grid 128, block 256. BM=64, BN=128, BK=32.
// =====================================================================
__global__ __launch_bounds__(256) void wh_gemm_kernel(
    const float* __restrict__ h, const float* __restrict__ Wm)
{
    __shared__ float hs[64][33];
    __shared__ float Ws[32][132];
    const int tid = threadIdx.x;
    const int i0  = blockIdx.x * 64;
    const int ty  = tid >> 4, tx = tid & 15;   // 16x16 threads; thread tile 4x8

    float acc[4][8];
#pragma unroll
    for (int u = 0; u < 4; u++)
#pragma unroll
        for (int v = 0; v < 8; v++) acc[u][v] = 0.0f;

    for (int k0 = 0; k0 < FIN; k0 += 32) {
        __syncthreads();
        {   // load h tile 64x32
            int r = tid >> 2, c = (tid & 3) * 8;
            float4 v0 = *(const float4*)&h[(size_t)(i0 + r) * FIN + k0 + c];
            float4 v1 = *(const float4*)&h[(size_t)(i0 + r) * FIN + k0 + c + 4];
            hs[r][c+0]=v0.x; hs[r][c+1]=v0.y; hs[r][c+2]=v0.z; hs[r][c+3]=v0.w;
            hs[r][c+4]=v1.x; hs[r][c+5]=v1.y; hs[r][c+6]=v1.z; hs[r][c+7]=v1.w;
        }
        {   // load W tile 32x128
            int r = tid >> 3, c = (tid & 7) * 16;
#pragma unroll
            for (int q = 0; q < 4; q++) {
                float4 v = *(const float4*)&Wm[(size_t)(k0 + r) * FOUT + c + 4*q];
                Ws[r][c+4*q+0]=v.x; Ws[r][c+4*q+1]=v.y; Ws[r][c+4*q+2]=v.z; Ws[r][c+4*q+3]=v.w;
            }
        }
        __syncthreads();
#pragma unroll 8
        for (int k = 0; k < 32; k++) {
            float av[4];
#pragma unroll
            for (int u = 0; u < 4; u++) av[u] = hs[4*ty + u][k];
            float4 b0 = *(const float4*)&Ws[k][8*tx];
            float4 b1 = *(const float4*)&Ws[k][8*tx + 4];
            float bv[8] = {b0.x,b0.y,b0.z,b0.w,b1.x,b1.y,b1.z,b1.w};
#pragma unroll
            for (int u = 0; u < 4; u++)
#pragma unroll
                for (int v = 0; v < 8; v++)
                    acc[u][v] = fmaf(av[u], bv[v], acc[u][v]);
        }
    }
    // epilogue: fp32 + bf16 hi/lo split
#pragma unroll
    for (int u = 0; u < 4; u++) {
        int row = i0 + 4*ty + u;
#pragma unroll
        for (int v = 0; v < 8; v++) {
            int col = 8*tx + v;
            float val = acc[u][v];
            size_t idx = (size_t)row * FOUT + col;
            g_Wh[idx] = val;
            __nv_bfloat16 hi = __float2bfloat16(val);
            g_WhH[idx] = hi;
            g_WhL[idx] = __float2bfloat16(val - __bfloat162float(hi));
        }
    }
}

// =====================================================================
// Kernel 2: f1 = Wh@a1, f2 = Wh@a2, and the 4 exp vectors.
// 1 warp per row; grid 1024 x 256.
// =====================================================================
__global__ __launch_bounds__(256) void f_exp_kernel(const float* __restrict__ a)
{
    const int lane = threadIdx.x & 31;
    const int warp = threadIdx.x >> 5;
    const int i = blockIdx.x * 8 + warp;
    const float* wh = &g_Wh[(size_t)i * FOUT];

    float f1 = 0.0f, f2 = 0.0f;
#pragma unroll
    for (int u = 0; u < 4; u++) {
        int k = lane + 32 * u;
        float w = wh[k];
        f1 = fmaf(w, a[k],        f1);
        f2 = fmaf(w, a[FOUT + k], f2);
    }
#pragma unroll
    for (int o = 16; o > 0; o >>= 1) {
        f1 += __shfl_xor_sync(0xffffffffu, f1, o);
        f2 += __shfl_xor_sync(0xffffffffu, f2, o);
    }
    if (lane == 0) {
        g_nf1[i] = -f1;
        g_E1[i]  = expf(f1);
        g_G1[i]  = expf(0.2f * f1);
        g_f2[i]  = f2;
        g_E2[i]  = expf(f2);
        g_G2[i]  = expf(0.2f * f2);
    }
}

// =====================================================================
// Kernel 3: fused masked-softmax-attention GEMM.
// CTA = 64 rows. Loop over 128 j-chunks of 64:
//   P-gen (adj int4 prefetched 1 chunk ahead) -> bf16 SMEM + fp32 row sums
//   Wh hi/lo tiles via cp.async
//   8 warps x (m32 x n32) mma.sync.m16n8k16 bf16, fp32 accum
// Epilogue: divide by row sum.
// =====================================================================
__device__ __forceinline__ void mma_bf16(float* c, const uint32_t* a,
                                         uint32_t b0, uint32_t b1)
{
    asm volatile(
        "mma.sync.aligned.m16n8k16.row.col.f32.bf16.bf16.f32 "
        "{%0,%1,%2,%3},{%4,%5,%6,%7},{%8,%9},{%0,%1,%2,%3};\n"
        : "+f"(c[0]), "+f"(c[1]), "+f"(c[2]), "+f"(c[3])
        : "r"(a[0]), "r"(a[1]), "r"(a[2]), "r"(a[3]), "r"(b0), "r"(b1));
}

__global__ __launch_bounds__(256, 1) void gat_main_kernel(
    const int* __restrict__ adj, float* __restrict__ out)
{
    __shared__ __nv_bfloat16 sP [64][72];    // P tile, padded for ldmatrix
    __shared__ __nv_bfloat16 sBH[64][136];   // Wh hi tile [k][n]
    __shared__ __nv_bfloat16 sBL[64][136];   // Wh lo tile
    __shared__ float sden[64];

    const int tid  = threadIdx.x;
    const int lane = tid & 31;
    const int warp = tid >> 5;
    const int i0   = blockIdx.x * 64;
    const int rr   = tid >> 4;      // 0..15 (row-within-pass)
    const int cg   = tid & 15;      // col group (4 ints)
    const int wm   = warp & 1;      // m32 position
    const int wn   = warp >> 1;     // n32 position

    if (tid < 64) sden[tid] = 0.0f;

    // per-thread row constants (rows p*16 + rr, p=0..3)
    float nf1r[4], E1r[4], G1r[4];
#pragma unroll
    for (int p = 0; p < 4; p++) {
        int r = p * 16 + rr;
        nf1r[p] = g_nf1[i0 + r];
        E1r[p]  = g_E1 [i0 + r];
        G1r[p]  = g_G1 [i0 + r];
    }

    // prefetch adj for chunk 0
    int4 adjreg[4];
#pragma unroll
    for (int p = 0; p < 4; p++) {
        int r = p * 16 + rr;
        adjreg[p] = *(const int4*)&adj[(size_t)(i0 + r) * NN + 4 * cg];
    }

    float acc[2][4][4];
#pragma unroll
    for (int mf = 0; mf < 2; mf++)
#pragma unroll
        for (int nf = 0; nf < 4; nf++)
#pragma unroll
            for (int q = 0; q < 4; q++) acc[mf][nf][q] = 0.0f;

    for (int ch = 0; ch < NC; ch++) {
        const int j0 = ch * 64;
        __syncthreads();   // prev MMA done; safe to overwrite tiles

        // ---- stage Wh hi/lo tiles via cp.async ----
#pragma unroll
        for (int it = 0; it < 4; it++) {
            int seg = tid + 256 * it;
            int r = seg >> 4, s = seg & 15;
            const __nv_bfloat16* srcH = &g_WhH[(size_t)(j0 + r) * FOUT + s * 8];
            const __nv_bfloat16* srcL = &g_WhL[(size_t)(j0 + r) * FOUT + s * 8];
            uint32_t dH = sptr(&sBH[r][s * 8]);
            uint32_t dL = sptr(&sBL[r][s * 8]);
            asm volatile("cp.async.cg.shared.global [%0],[%1],16;\n" :: "r"(dH), "l"(srcH));
            asm volatile("cp.async.cg.shared.global [%0],[%1],16;\n" :: "r"(dL), "l"(srcL));
        }
        asm volatile("cp.async.commit_group;\n");

        // ---- P generation + denominator partial sums ----
#pragma unroll
        for (int p = 0; p < 4; p++) {
            int r  = p * 16 + rr;
            int c0 = 4 * cg;
            float4 f2v = *(const float4*)&g_f2[j0 + c0];
            float4 E2v = *(const float4*)&g_E2[j0 + c0];
            float4 G2v = *(const float4*)&g_G2[j0 + c0];
            int4 av = adjreg[p];
            float tnf = nf1r[p], e1 = E1r[p], g1 = G1r[p];
            float w0 = (av.x > 0) ? ((f2v.x > tnf) ? e1 * E2v.x : g1 * G2v.x) : 0.0f;
            float w1 = (av.y > 0) ? ((f2v.y > tnf) ? e1 * E2v.y : g1 * G2v.y) : 0.0f;
            float w2 = (av.z > 0) ? ((f2v.z > tnf) ? e1 * E2v.z : g1 * G2v.z) : 0.0f;
            float w3 = (av.w > 0) ? ((f2v.w > tnf) ? e1 * E2v.w : g1 * G2v.w) : 0.0f;
            __nv_bfloat16 h0 = __float2bfloat16(w0);
            __nv_bfloat16 h1 = __float2bfloat16(w1);
            __nv_bfloat16 h2 = __float2bfloat16(w2);
            __nv_bfloat16 h3 = __float2bfloat16(w3);
            *(__nv_bfloat162*)&sP[r][c0]     = __halves2bfloat162(h0, h1);
            *(__nv_bfloat162*)&sP[r][c0 + 2] = __halves2bfloat162(h2, h3);
            // denominator uses the SAME bf16-rounded weights the MMA sees
            float ds = __bfloat162float(h0) + __bfloat162float(h1)
                     + __bfloat162float(h2) + __bfloat162float(h3);
            ds += __shfl_xor_sync(0xffffffffu, ds, 8);
            ds += __shfl_xor_sync(0xffffffffu, ds, 4);
            ds += __shfl_xor_sync(0xffffffffu, ds, 2);
            ds += __shfl_xor_sync(0xffffffffu, ds, 1);
            if (cg == 0) sden[r] += ds;   // unique writer per (r)
        }

        // ---- prefetch adj for next chunk ----
        if (ch + 1 < NC) {
            int j1 = j0 + 64;
#pragma unroll
            for (int p = 0; p < 4; p++) {
                int r = p * 16 + rr;
                adjreg[p] = *(const int4*)&adj[(size_t)(i0 + r) * NN + j1 + 4 * cg];
            }
        }

        asm volatile("cp.async.wait_group 0;\n");
        __syncthreads();

        // ---- MMA phase: warp tile m32 x n32, K=64 in 4 steps ----
#pragma unroll
        for (int kk = 0; kk < 4; kk++) {
            uint32_t afr[2][4];
            {
                int mi   = lane >> 3;
                int rsub = ((mi & 1) << 3) + (lane & 7);
                int csub = (mi >> 1) << 3;
#pragma unroll
                for (int mf = 0; mf < 2; mf++) {
                    uint32_t addr = sptr(&sP[32*wm + 16*mf + rsub][16*kk + csub]);
                    asm volatile(
                        "ldmatrix.sync.aligned.m8n8.x4.shared.b16 {%0,%1,%2,%3},[%4];\n"
                        : "=r"(afr[mf][0]), "=r"(afr[mf][1]),
                          "=r"(afr[mf][2]), "=r"(afr[mf][3])
                        : "r"(addr));
                }
            }
            int rowb = 16 * kk + (lane & 15);
#pragma unroll
            for (int nf = 0; nf < 4; nf++) {
                int n0 = 32 * wn + 8 * nf;
                uint32_t bh0, bh1, bl0, bl1;
                uint32_t baH = sptr(&sBH[rowb][n0]);
                uint32_t baL = sptr(&sBL[rowb][n0]);
                asm volatile(
                    "ldmatrix.sync.aligned.m8n8.x2.trans.shared.b16 {%0,%1},[%2];\n"
                    : "=r"(bh0), "=r"(bh1) : "r"(baH));
                asm volatile(
                    "ldmatrix.sync.aligned.m8n8.x2.trans.shared.b16 {%0,%1},[%2];\n"
                    : "=r"(bl0), "=r"(bl1) : "r"(baL));
#pragma unroll
                for (int mf = 0; mf < 2; mf++) {
                    mma_bf16(acc[mf][nf], afr[mf], bh0, bh1);
                    mma_bf16(acc[mf][nf], afr[mf], bl0, bl1);
                }
            }
        }
    }

    __syncthreads();
    // ---- epilogue: divide by row sums, write fp32 output ----
    const int g = lane >> 2, t = lane & 3;
#pragma unroll
    for (int mf = 0; mf < 2; mf++) {
        int lr0 = 32 * wm + 16 * mf + g;
        float inv0 = 1.0f / sden[lr0];
        float inv1 = 1.0f / sden[lr0 + 8];
#pragma unroll
        for (int nf = 0; nf < 4; nf++) {
            int col = 32 * wn + 8 * nf + 2 * t;
            out[(size_t)(i0 + lr0)     * FOUT + col    ] = acc[mf][nf][0] * inv0;
            out[(size_t)(i0 + lr0)     * FOUT + col + 1] = acc[mf][nf][1] * inv0;
            out[(size_t)(i0 + lr0 + 8) * FOUT + col    ] = acc[mf][nf][2] * inv1;
            out[(size_t)(i0 + lr0 + 8) * FOUT + col + 1] = acc[mf][nf][3] * inv1;
        }
    }
}

// =====================================================================
extern "C" void kernel_launch(void* const* d_in, const int* in_sizes, int n_in,
                              void* d_out, int out_size)
{
    const float* h   = (const float*)d_in[0];   // [8192,256] f32
    const int*   adj = (const int*)  d_in[1];   // [8192,8192] i32
    const float* Wm  = (const float*)d_in[2];   // [256,128] f32
    const float* a   = (const float*)d_in[3];   // [256,1] f32
    float* out = (float*)d_out;                 // [8192,128] f32

    wh_gemm_kernel <<<128, 256>>>(h, Wm);
    f_exp_kernel   <<<1024, 256>>>(a);
    gat_main_kernel<<<128, 256>>>(adj, out);
}

// round 4
// speedup vs baseline: 1.2146x; 1.2146x over previous
#include <cuda_runtime.h>
#include <cuda_fp16.h>
#include <cstdint>

#define NN   8192
#define FIN  256
#define FOUT 128
#define NC   128        // j-chunks of 64
#define BM   64         // rows per CTA in main kernel
#define GRID_MAIN (NN / BM)   // 128

// ---------------- scratch (static device globals; no allocation) ----------------
__device__ __align__(16) __half g_Wh16[(size_t)NN * FOUT];  // [row j][col c] fp16
__device__ __align__(16) float g_nf1[NN];   // -f1
__device__ __align__(16) float g_H1 [NN];   // exp(-0.8 f1)
__device__ __align__(16) float g_f2 [NN];
__device__ __align__(16) float g_E2 [NN];   // exp(f2)
__device__ __align__(16) float g_G2 [NN];   // exp(0.2 f2)

__device__ __forceinline__ uint32_t sptr(const void* p) {
    return (uint32_t)__cvta_generic_to_shared(p);
}

// =====================================================================
// Kernel 1: Wh = h @ W (fp32 SIMT GEMM) fused with fp16 output and the
// f1/f2 row reductions + exp vectors. grid 256, block 256. BM=32.
// =====================================================================
__global__ __launch_bounds__(256) void wh_gemm_kernel(
    const float* __restrict__ h, const float* __restrict__ Wm,
    const float* __restrict__ a)
{
    __shared__ float hs[32][33];
    __shared__ float Ws[32][132];
    const int tid = threadIdx.x;
    const int i0  = blockIdx.x * 32;
    const int ty  = tid >> 4, tx = tid & 15;

    float acc[2][8];
#pragma unroll
    for (int u = 0; u < 2; u++)
#pragma unroll
        for (int v = 0; v < 8; v++) acc[u][v] = 0.0f;

    for (int k0 = 0; k0 < FIN; k0 += 32) {
        __syncthreads();
        {   // h tile 32x32
            int r = tid >> 3, c = (tid & 7) * 4;
            float4 v = *(const float4*)&h[(size_t)(i0 + r) * FIN + k0 + c];
            hs[r][c+0]=v.x; hs[r][c+1]=v.y; hs[r][c+2]=v.z; hs[r][c+3]=v.w;
        }
        {   // W tile 32x128
            int r = tid >> 3, c = (tid & 7) * 16;
#pragma unroll
            for (int q = 0; q < 4; q++) {
                float4 v = *(const float4*)&Wm[(size_t)(k0 + r) * FOUT + c + 4*q];
                Ws[r][c+4*q+0]=v.x; Ws[r][c+4*q+1]=v.y; Ws[r][c+4*q+2]=v.z; Ws[r][c+4*q+3]=v.w;
            }
        }
        __syncthreads();
#pragma unroll 8
        for (int k = 0; k < 32; k++) {
            float a0 = hs[2*ty][k], a1 = hs[2*ty+1][k];
            float4 b0 = *(const float4*)&Ws[k][8*tx];
            float4 b1 = *(const float4*)&Ws[k][8*tx + 4];
            float bv[8] = {b0.x,b0.y,b0.z,b0.w,b1.x,b1.y,b1.z,b1.w};
#pragma unroll
            for (int v = 0; v < 8; v++) {
                acc[0][v] = fmaf(a0, bv[v], acc[0][v]);
                acc[1][v] = fmaf(a1, bv[v], acc[1][v]);
            }
        }
    }

    // ---- epilogue: fp16 Wh + f1/f2 + exps ----
    float f1a[2] = {0.f, 0.f}, f2a[2] = {0.f, 0.f};
#pragma unroll
    for (int u = 0; u < 2; u++) {
        int row = i0 + 2*ty + u;
#pragma unroll
        for (int q = 0; q < 4; q++) {
            float v0 = acc[u][2*q], v1 = acc[u][2*q+1];
            *(__half2*)&g_Wh16[(size_t)row * FOUT + 8*tx + 2*q] =
                __floats2half2_rn(v0, v1);
        }
#pragma unroll
        for (int v = 0; v < 8; v++) {
            int col = 8*tx + v;
            f1a[u] = fmaf(acc[u][v], a[col],        f1a[u]);
            f2a[u] = fmaf(acc[u][v], a[FOUT + col], f2a[u]);
        }
    }
#pragma unroll
    for (int o = 8; o > 0; o >>= 1) {
        f1a[0] += __shfl_xor_sync(0xffffffffu, f1a[0], o);
        f1a[1] += __shfl_xor_sync(0xffffffffu, f1a[1], o);
        f2a[0] += __shfl_xor_sync(0xffffffffu, f2a[0], o);
        f2a[1] += __shfl_xor_sync(0xffffffffu, f2a[1], o);
    }
    if (tx == 0) {
#pragma unroll
        for (int u = 0; u < 2; u++) {
            int i = i0 + 2*ty + u;
            float f1 = f1a[u], f2 = f2a[u];
            g_nf1[i] = -f1;
            g_H1[i]  = expf(-0.8f * f1);
            g_f2[i]  = f2;
            g_E2[i]  = expf(f2);
            g_G2[i]  = expf(0.2f * f2);
        }
    }
}

// =====================================================================
// Kernel 2: fused masked-softmax-attention, fp16 mma.sync, pipelined.
// CTA = 64 rows, grid 128, 256 thr (8 warps, 2m x 4n, warp m32n32).
// Row-rescaled weights (softmax-invariant): pos=E2_j, neg=H1_i*G2_j.
// Double-buffered sP/sB; stage(ch+1) issued before MMA(ch) consumes.
// =====================================================================
__device__ __forceinline__ void mma_fp16(float* c, const uint32_t* a,
                                         uint32_t b0, uint32_t b1)
{
    asm volatile(
        "mma.sync.aligned.m16n8k16.row.col.f32.f16.f16.f32 "
        "{%0,%1,%2,%3},{%4,%5,%6,%7},{%8,%9},{%0,%1,%2,%3};\n"
        : "+f"(c[0]), "+f"(c[1]), "+f"(c[2]), "+f"(c[3])
        : "r"(a[0]), "r"(a[1]), "r"(a[2]), "r"(a[3]), "r"(b0), "r"(b1));
}

#define SP_BYTES 9216u                  // 64 x 72 halfs
#define SB_BYTES 17408u                 // 64 x 136 halfs
#define DYN_SMEM (2*SP_BYTES + 2*SB_BYTES)   // 53248

__global__ __launch_bounds__(256, 1) void gat_main_kernel(
    const int* __restrict__ adj, float* __restrict__ out)
{
    extern __shared__ char dynsm[];
    __shared__ float sden[BM];

    const int tid  = threadIdx.x;
    const int lane = tid & 31;
    const int warp = tid >> 5;
    const int rr   = tid >> 4;     // 0..15
    const int cg   = tid & 15;     // col group of 4
    const int i0   = blockIdx.x * BM;
    const int wm   = warp & 1;     // m32 position
    const int wn   = warp >> 1;    // n32 position

    auto sPb = [&](int b) { return (__half(*)[72]) (dynsm + (uint32_t)b * SP_BYTES); };
    auto sBb = [&](int b) { return (__half(*)[136])(dynsm + 2*SP_BYTES + (uint32_t)b * SB_BYTES); };

    // per-thread row constants for the 4 row-groups (rows 16p+rr)
    float nf1r[4], H1r[4];
#pragma unroll
    for (int p = 0; p < 4; p++) {
        int r = i0 + 16*p + rr;
        nf1r[p] = g_nf1[r];
        H1r[p]  = g_H1[r];
    }
    float denacc[4] = {0.f, 0.f, 0.f, 0.f};

    float acc[2][4][4];
#pragma unroll
    for (int mf = 0; mf < 2; mf++)
#pragma unroll
        for (int nf = 0; nf < 4; nf++)
#pragma unroll
            for (int q = 0; q < 4; q++) acc[mf][nf][q] = 0.0f;

    // ---- helpers ----
    auto stage_B = [&](int j0, int b) {
        __half (*sB)[136] = sBb(b);
#pragma unroll
        for (int it = 0; it < 4; it++) {
            int seg = tid + 256 * it;          // 0..1023
            int r = seg >> 4, s = seg & 15;
            const __half* src = &g_Wh16[(size_t)(j0 + r) * FOUT + 8*s];
            uint32_t dst = sptr(&sB[r][8*s]);
            asm volatile("cp.async.cg.shared.global [%0],[%1],16;\n" :: "r"(dst), "l"(src));
        }
        asm volatile("cp.async.commit_group;\n");
    };

    auto pgen = [&](int j0, int b, const int4* av) {
        __half (*sP)[72] = sPb(b);
        float4 f2v = *(const float4*)&g_f2[j0 + 4*cg];
        float4 E2v = *(const float4*)&g_E2[j0 + 4*cg];
        float4 G2v = *(const float4*)&g_G2[j0 + 4*cg];
#pragma unroll
        for (int p = 0; p < 4; p++) {
            int r = 16*p + rr;
            float tnf = nf1r[p], h1 = H1r[p];
            float w0 = (av[p].x > 0) ? ((f2v.x > tnf) ? E2v.x : h1 * G2v.x) : 0.0f;
            float w1 = (av[p].y > 0) ? ((f2v.y > tnf) ? E2v.y : h1 * G2v.y) : 0.0f;
            float w2 = (av[p].z > 0) ? ((f2v.z > tnf) ? E2v.z : h1 * G2v.z) : 0.0f;
            float w3 = (av[p].w > 0) ? ((f2v.w > tnf) ? E2v.w : h1 * G2v.w) : 0.0f;
            w0 = fminf(w0, 60000.f); w1 = fminf(w1, 60000.f);
            w2 = fminf(w2, 60000.f); w3 = fminf(w3, 60000.f);
            __half2 pk0 = __floats2half2_rn(w0, w1);
            __half2 pk1 = __floats2half2_rn(w2, w3);
            uint32_t u0 = *(uint32_t*)&pk0, u1 = *(uint32_t*)&pk1;
            asm volatile("st.shared.v2.b32 [%0], {%1,%2};"
                         :: "r"(sptr(&sP[r][4*cg])), "r"(u0), "r"(u1) : "memory");
            // denominator from the SAME fp16-rounded weights the MMA sees
            denacc[p] += __low2float(pk0) + __high2float(pk0)
                       + __low2float(pk1) + __high2float(pk1);
        }
    };

    auto mma_phase = [&](int b) {
        __half (*sP)[72]  = sPb(b);
        __half (*sB)[136] = sBb(b);
#pragma unroll
        for (int kk = 0; kk < 4; kk++) {
            uint32_t afr[2][4];
            int mi   = lane >> 3;
            int rsub = ((mi & 1) << 3) + (lane & 7);
            int csub = (mi >> 1) << 3;
#pragma unroll
            for (int mf = 0; mf < 2; mf++) {
                uint32_t addr = sptr(&sP[32*wm + 16*mf + rsub][16*kk + csub]);
                asm volatile(
                    "ldmatrix.sync.aligned.m8n8.x4.shared.b16 {%0,%1,%2,%3},[%4];\n"
                    : "=r"(afr[mf][0]), "=r"(afr[mf][1]),
                      "=r"(afr[mf][2]), "=r"(afr[mf][3])
                    : "r"(addr));
            }
            int rowb = 16*kk + (lane & 15);
#pragma unroll
            for (int nf = 0; nf < 4; nf++) {
                uint32_t b0, b1;
                uint32_t ba = sptr(&sB[rowb][32*wn + 8*nf]);
                asm volatile(
                    "ldmatrix.sync.aligned.m8n8.x2.trans.shared.b16 {%0,%1},[%2];\n"
                    : "=r"(b0), "=r"(b1) : "r"(ba));
#pragma unroll
                for (int mf = 0; mf < 2; mf++)
                    mma_fp16(acc[mf][nf], afr[mf], b0, b1);
            }
        }
    };

    // ---- prologue: stage chunk 0 ----
    int4 adjN[4];
#pragma unroll
    for (int p = 0; p < 4; p++)
        adjN[p] = *(const int4*)&adj[(size_t)(i0 + 16*p + rr) * NN + 4*cg];
    stage_B(0, 0);
    pgen(0, 0, adjN);
#pragma unroll
    for (int p = 0; p < 4; p++)
        adjN[p] = *(const int4*)&adj[(size_t)(i0 + 16*p + rr) * NN + 64 + 4*cg];
    asm volatile("cp.async.wait_group 0;\n");
    __syncthreads();

    // ---- main pipelined loop ----
    for (int ch = 0; ch < NC; ch++) {
        const int cur = ch & 1;
        if (ch + 1 < NC) {
            stage_B((ch + 1) * 64, cur ^ 1);
            pgen((ch + 1) * 64, cur ^ 1, adjN);
            if (ch + 2 < NC) {
                int j2 = (ch + 2) * 64;
#pragma unroll
                for (int p = 0; p < 4; p++)
                    adjN[p] = *(const int4*)&adj[(size_t)(i0 + 16*p + rr) * NN + j2 + 4*cg];
            }
        }
        mma_phase(cur);
        asm volatile("cp.async.wait_group 0;\n");
        __syncthreads();
    }

    // ---- denominator final reduction (over cg lanes) ----
#pragma unroll
    for (int p = 0; p < 4; p++) {
#pragma unroll
        for (int o = 8; o > 0; o >>= 1)
            denacc[p] += __shfl_xor_sync(0xffffffffu, denacc[p], o);
        if ((lane & 15) == 0) sden[16*p + rr] = denacc[p];
    }
    __syncthreads();

    // ---- epilogue: normalize, write fp32 output ----
    const int g = lane >> 2, t = lane & 3;
#pragma unroll
    for (int mf = 0; mf < 2; mf++) {
        int lr0 = 32*wm + 16*mf + g;
        float inv0 = 1.0f / sden[lr0];
        float inv1 = 1.0f / sden[lr0 + 8];
#pragma unroll
        for (int nf = 0; nf < 4; nf++) {
            int col = 32*wn + 8*nf + 2*t;
            out[(size_t)(i0 + lr0)     * FOUT + col    ] = acc[mf][nf][0] * inv0;
            out[(size_t)(i0 + lr0)     * FOUT + col + 1] = acc[mf][nf][1] * inv0;
            out[(size_t)(i0 + lr0 + 8) * FOUT + col    ] = acc[mf][nf][2] * inv1;
            out[(size_t)(i0 + lr0 + 8) * FOUT + col + 1] = acc[mf][nf][3] * inv1;
        }
    }
}

// =====================================================================
extern "C" void kernel_launch(void* const* d_in, const int* in_sizes, int n_in,
                              void* d_out, int out_size)
{
    const float* h   = (const float*)d_in[0];   // [8192,256] f32
    const int*   adj = (const int*)  d_in[1];   // [8192,8192] i32
    const float* Wm  = (const float*)d_in[2];   // [256,128] f32
    const float* a   = (const float*)d_in[3];   // [256,1] f32
    float* out = (float*)d_out;                 // [8192,128] f32

    cudaFuncSetAttribute(gat_main_kernel,
                         cudaFuncAttributeMaxDynamicSharedMemorySize, DYN_SMEM);

    wh_gemm_kernel <<<256, 256>>>(h, Wm, a);
    gat_main_kernel<<<GRID_MAIN, 256, DYN_SMEM>>>(adj, out);
}

// round 5
// speedup vs baseline: 1.3193x; 1.0862x over previous
#include <cuda_runtime.h>
#include <cuda_fp16.h>
#include <cstdint>

#define NN   8192
#define FIN  256
#define FOUT 128
#define NC   128        // j-chunks of 64
#define BM   64         // rows per CTA in main kernel
#define GRID_MAIN (NN / BM)   // 128

// ---------------- scratch (static device globals; no allocation) ----------------
__device__ __align__(16) __half g_Wh16[(size_t)NN * FOUT];  // [row j][col c] fp16
__device__ __align__(16) float g_nf1[NN];   // -f1
__device__ __align__(16) float g_H1 [NN];   // exp(-0.8 f1)
__device__ __align__(16) float g_f2 [NN];
__device__ __align__(16) float g_E2 [NN];   // exp(f2)
__device__ __align__(16) float g_G2 [NN];   // exp(0.2 f2)

__device__ __forceinline__ uint32_t sptr(const void* p) {
    return (uint32_t)__cvta_generic_to_shared(p);
}

// =====================================================================
// Kernel 1: Wh = h @ W (fp32 SIMT GEMM) fused with fp16 output and the
// f1/f2 row reductions + exp vectors. grid 256, block 256. BM=32.
// =====================================================================
__global__ __launch_bounds__(256) void wh_gemm_kernel(
    const float* __restrict__ h, const float* __restrict__ Wm,
    const float* __restrict__ a)
{
    __shared__ float hs[32][33];
    __shared__ float Ws[32][132];
    const int tid = threadIdx.x;
    const int i0  = blockIdx.x * 32;
    const int ty  = tid >> 4, tx = tid & 15;

    float acc[2][8];
#pragma unroll
    for (int u = 0; u < 2; u++)
#pragma unroll
        for (int v = 0; v < 8; v++) acc[u][v] = 0.0f;

    for (int k0 = 0; k0 < FIN; k0 += 32) {
        __syncthreads();
        {   int r = tid >> 3, c = (tid & 7) * 4;
            float4 v = *(const float4*)&h[(size_t)(i0 + r) * FIN + k0 + c];
            hs[r][c+0]=v.x; hs[r][c+1]=v.y; hs[r][c+2]=v.z; hs[r][c+3]=v.w;
        }
        {   int r = tid >> 3, c = (tid & 7) * 16;
#pragma unroll
            for (int q = 0; q < 4; q++) {
                float4 v = *(const float4*)&Wm[(size_t)(k0 + r) * FOUT + c + 4*q];
                Ws[r][c+4*q+0]=v.x; Ws[r][c+4*q+1]=v.y; Ws[r][c+4*q+2]=v.z; Ws[r][c+4*q+3]=v.w;
            }
        }
        __syncthreads();
#pragma unroll 8
        for (int k = 0; k < 32; k++) {
            float a0 = hs[2*ty][k], a1 = hs[2*ty+1][k];
            float4 b0 = *(const float4*)&Ws[k][8*tx];
            float4 b1 = *(const float4*)&Ws[k][8*tx + 4];
            float bv[8] = {b0.x,b0.y,b0.z,b0.w,b1.x,b1.y,b1.z,b1.w};
#pragma unroll
            for (int v = 0; v < 8; v++) {
                acc[0][v] = fmaf(a0, bv[v], acc[0][v]);
                acc[1][v] = fmaf(a1, bv[v], acc[1][v]);
            }
        }
    }

    float f1a[2] = {0.f, 0.f}, f2a[2] = {0.f, 0.f};
#pragma unroll
    for (int u = 0; u < 2; u++) {
        int row = i0 + 2*ty + u;
#pragma unroll
        for (int q = 0; q < 4; q++) {
            *(__half2*)&g_Wh16[(size_t)row * FOUT + 8*tx + 2*q] =
                __floats2half2_rn(acc[u][2*q], acc[u][2*q+1]);
        }
#pragma unroll
        for (int v = 0; v < 8; v++) {
            int col = 8*tx + v;
            f1a[u] = fmaf(acc[u][v], a[col],        f1a[u]);
            f2a[u] = fmaf(acc[u][v], a[FOUT + col], f2a[u]);
        }
    }
#pragma unroll
    for (int o = 8; o > 0; o >>= 1) {
        f1a[0] += __shfl_xor_sync(0xffffffffu, f1a[0], o);
        f1a[1] += __shfl_xor_sync(0xffffffffu, f1a[1], o);
        f2a[0] += __shfl_xor_sync(0xffffffffu, f2a[0], o);
        f2a[1] += __shfl_xor_sync(0xffffffffu, f2a[1], o);
    }
    if (tx == 0) {
#pragma unroll
        for (int u = 0; u < 2; u++) {
            int i = i0 + 2*ty + u;
            float f1 = f1a[u], f2 = f2a[u];
            g_nf1[i] = -f1;
            g_H1[i]  = expf(-0.8f * f1);
            g_f2[i]  = f2;
            g_E2[i]  = expf(f2);
            g_G2[i]  = expf(0.2f * f2);
        }
    }
}

// =====================================================================
// Kernel 2: fused masked-softmax-attention, fp16 mma.sync.
// 512 threads (16 warps, 4m x 4n, warp tile m16n32), BM=64, grid 128.
// adj streamed via cp.async 4-deep SMEM ring (self-consumed -> no barrier);
// sP/sB triple-buffered; counted cp.async groups; 1 barrier per chunk.
// =====================================================================
__device__ __forceinline__ void mma_fp16(float* c, const uint32_t* a,
                                         uint32_t b0, uint32_t b1)
{
    asm volatile(
        "mma.sync.aligned.m16n8k16.row.col.f32.f16.f16.f32 "
        "{%0,%1,%2,%3},{%4,%5,%6,%7},{%8,%9},{%0,%1,%2,%3};\n"
        : "+f"(c[0]), "+f"(c[1]), "+f"(c[2]), "+f"(c[3])
        : "r"(a[0]), "r"(a[1]), "r"(a[2]), "r"(a[3]), "r"(b0), "r"(b1));
}

#define ADJ_SLOT 16384u      // 64 x 64 ints
#define SP_SLOT  9216u       // 64 x 72 halfs
#define SB_SLOT  17408u      // 64 x 136 halfs
#define DYN_SMEM (4*ADJ_SLOT + 3*SP_SLOT + 3*SB_SLOT)   // 145408

__global__ __launch_bounds__(512, 1) void gat_main_kernel(
    const int* __restrict__ adj, float* __restrict__ out)
{
    extern __shared__ char dynsm[];
    __shared__ float sden[BM];

    const int tid  = threadIdx.x;
    const int lane = tid & 31;
    const int warp = tid >> 5;
    const int r    = tid >> 3;     // 0..63  (pgen/adj row)
    const int cb   = tid & 7;      // col block of 8
    const int i0   = blockIdx.x * BM;
    const int wm   = warp & 3;     // m16 position
    const int wn   = warp >> 2;    // n32 position

    const uint32_t adjS = sptr(dynsm);
    const uint32_t spS  = adjS + 4 * ADJ_SLOT;
    const uint32_t sbS  = spS  + 3 * SP_SLOT;

    const float nf1r = g_nf1[i0 + r];
    const float H1r  = g_H1 [i0 + r];
    float den = 0.0f;

    float acc[4][4];
#pragma unroll
    for (int nf = 0; nf < 4; nf++)
#pragma unroll
        for (int q = 0; q < 4; q++) acc[nf][q] = 0.0f;

    // ---- stage helpers (each always commits exactly one group) ----
    auto stage_adj = [&](int ch) {
        if (ch < NC) {
            const int* src = &adj[(size_t)(i0 + r) * NN + ch * 64 + 8 * cb];
            uint32_t dst = adjS + (uint32_t)(ch & 3) * ADJ_SLOT
                         + (uint32_t)(r * 256 + 32 * cb);
            asm volatile("cp.async.cg.shared.global [%0],[%1],16;\n" :: "r"(dst), "l"(src));
            asm volatile("cp.async.cg.shared.global [%0],[%1],16;\n" :: "r"(dst+16u), "l"(src+4));
        }
        asm volatile("cp.async.commit_group;\n");
    };
    auto stage_B = [&](int ch) {
        if (ch < NC) {
            const int j0 = ch * 64;
            uint32_t base = sbS + (uint32_t)(ch % 3) * SB_SLOT;
#pragma unroll
            for (int i = 0; i < 2; i++) {
                int seg = tid + 512 * i;          // 0..1023
                int rr = seg >> 4, ss = seg & 15;
                const __half* src = &g_Wh16[(size_t)(j0 + rr) * FOUT + 8 * ss];
                uint32_t dst = base + (uint32_t)(rr * 272 + 16 * ss);
                asm volatile("cp.async.cg.shared.global [%0],[%1],16;\n" :: "r"(dst), "l"(src));
            }
        }
        asm volatile("cp.async.commit_group;\n");
    };

    auto pgen = [&](int ch) {
        const int j0 = ch * 64, c0 = 8 * cb;
        uint32_t aoff = adjS + (uint32_t)(ch & 3) * ADJ_SLOT
                      + (uint32_t)(r * 256 + 32 * cb);
        int4 a0, a1;
        asm volatile("ld.shared.v4.b32 {%0,%1,%2,%3},[%4];"
                     : "=r"(a0.x), "=r"(a0.y), "=r"(a0.z), "=r"(a0.w) : "r"(aoff));
        asm volatile("ld.shared.v4.b32 {%0,%1,%2,%3},[%4];"
                     : "=r"(a1.x), "=r"(a1.y), "=r"(a1.z), "=r"(a1.w) : "r"(aoff + 16u));
        float4 f2v0 = *(const float4*)&g_f2[j0 + c0];
        float4 f2v1 = *(const float4*)&g_f2[j0 + c0 + 4];
        float4 E2v0 = *(const float4*)&g_E2[j0 + c0];
        float4 E2v1 = *(const float4*)&g_E2[j0 + c0 + 4];
        float4 G2v0 = *(const float4*)&g_G2[j0 + c0];
        float4 G2v1 = *(const float4*)&g_G2[j0 + c0 + 4];
        float w[8];
        w[0] = (a0.x > 0) ? ((f2v0.x > nf1r) ? E2v0.x : H1r * G2v0.x) : 0.0f;
        w[1] = (a0.y > 0) ? ((f2v0.y > nf1r) ? E2v0.y : H1r * G2v0.y) : 0.0f;
        w[2] = (a0.z > 0) ? ((f2v0.z > nf1r) ? E2v0.z : H1r * G2v0.z) : 0.0f;
        w[3] = (a0.w > 0) ? ((f2v0.w > nf1r) ? E2v0.w : H1r * G2v0.w) : 0.0f;
        w[4] = (a1.x > 0) ? ((f2v1.x > nf1r) ? E2v1.x : H1r * G2v1.x) : 0.0f;
        w[5] = (a1.y > 0) ? ((f2v1.y > nf1r) ? E2v1.y : H1r * G2v1.y) : 0.0f;
        w[6] = (a1.z > 0) ? ((f2v1.z > nf1r) ? E2v1.z : H1r * G2v1.z) : 0.0f;
        w[7] = (a1.w > 0) ? ((f2v1.w > nf1r) ? E2v1.w : H1r * G2v1.w) : 0.0f;
        uint32_t u[4];
#pragma unroll
        for (int q = 0; q < 4; q++) {
            __half2 pk = __floats2half2_rn(fminf(w[2*q], 60000.f),
                                           fminf(w[2*q+1], 60000.f));
            u[q] = *(uint32_t*)&pk;
            // denominator from the SAME fp16-rounded weights the MMA sees
            den += __low2float(pk) + __high2float(pk);
        }
        uint32_t dst = spS + (uint32_t)(ch % 3) * SP_SLOT
                     + (uint32_t)(r * 144 + c0 * 2);
        asm volatile("st.shared.v4.b32 [%0],{%1,%2,%3,%4};"
                     :: "r"(dst), "r"(u[0]), "r"(u[1]), "r"(u[2]), "r"(u[3]) : "memory");
    };

    auto mma_phase = [&](int ch) {
        uint32_t sp = spS + (uint32_t)(ch % 3) * SP_SLOT;
        uint32_t sb = sbS + (uint32_t)(ch % 3) * SB_SLOT;
        const int mi = lane >> 3, l7 = lane & 7;
#pragma unroll
        for (int kk = 0; kk < 4; kk++) {
            uint32_t afr[4];
            {
                uint32_t addr = sp + (uint32_t)((16*wm + ((mi & 1) << 3) + l7) * 144
                                                + (16*kk + ((mi >> 1) << 3)) * 2);
                asm volatile(
                    "ldmatrix.sync.aligned.m8n8.x4.shared.b16 {%0,%1,%2,%3},[%4];\n"
                    : "=r"(afr[0]), "=r"(afr[1]), "=r"(afr[2]), "=r"(afr[3])
                    : "r"(addr));
            }
#pragma unroll
            for (int nfp = 0; nfp < 2; nfp++) {
                int n0 = 32*wn + 16*nfp;
                uint32_t b[4];
                uint32_t addr = sb + (uint32_t)((16*kk + ((mi & 1) << 3) + l7) * 272
                                                + (n0 + ((mi >> 1) << 3)) * 2);
                asm volatile(
                    "ldmatrix.sync.aligned.m8n8.x4.trans.shared.b16 {%0,%1,%2,%3},[%4];\n"
                    : "=r"(b[0]), "=r"(b[1]), "=r"(b[2]), "=r"(b[3])
                    : "r"(addr));
                mma_fp16(acc[2*nfp],     afr, b[0], b[1]);
                mma_fp16(acc[2*nfp + 1], afr, b[2], b[3]);
            }
        }
    };

    // ---- prologue: commits [B0][A0][A1][A2][A3] ----
    stage_B(0);
    stage_adj(0); stage_adj(1); stage_adj(2); stage_adj(3);
    asm volatile("cp.async.wait_group 3;\n");   // A0 (and B0) complete
    pgen(0);

    // ---- main loop: commits per iter [A(ch+4)][B(ch+1)] ----
    for (int ch = 0; ch < NC; ch++) {
        stage_adj(ch + 4);
        stage_B(ch + 1);
        asm volatile("cp.async.wait_group 7;\n");   // A(ch+1) ready (self-consumed)
        if (ch + 1 < NC) pgen(ch + 1);
        asm volatile("cp.async.wait_group 2;\n");   // B(ch) writes complete
        __syncthreads();                            // B(ch)+P(ch) visible to all
        mma_phase(ch);
    }

    // ---- denominator reduction (8 threads per row) ----
    den += __shfl_xor_sync(0xffffffffu, den, 1);
    den += __shfl_xor_sync(0xffffffffu, den, 2);
    den += __shfl_xor_sync(0xffffffffu, den, 4);
    if (cb == 0) sden[r] = den;
    __syncthreads();

    // ---- epilogue: normalize, write fp32 output ----
    const int g = lane >> 2, t = lane & 3;
    {
        int row0 = 16*wm + g;
        float inv0 = 1.0f / sden[row0];
        float inv1 = 1.0f / sden[row0 + 8];
#pragma unroll
        for (int nf = 0; nf < 4; nf++) {
            int col = 32*wn + 8*nf + 2*t;
            out[(size_t)(i0 + row0)     * FOUT + col    ] = acc[nf][0] * inv0;
            out[(size_t)(i0 + row0)     * FOUT + col + 1] = acc[nf][1] * inv0;
            out[(size_t)(i0 + row0 + 8) * FOUT + col    ] = acc[nf][2] * inv1;
            out[(size_t)(i0 + row0 + 8) * FOUT + col + 1] = acc[nf][3] * inv1;
        }
    }
}

// =====================================================================
extern "C" void kernel_launch(void* const* d_in, const int* in_sizes, int n_in,
                              void* d_out, int out_size)
{
    const float* h   = (const float*)d_in[0];   // [8192,256] f32
    const int*   adj = (const int*)  d_in[1];   // [8192,8192] i32
    const float* Wm  = (const float*)d_in[2];   // [256,128] f32
    const float* a   = (const float*)d_in[3];   // [256,1] f32
    float* out = (float*)d_out;                 // [8192,128] f32

    cudaFuncSetAttribute(gat_main_kernel,
                         cudaFuncAttributeMaxDynamicSharedMemorySize, DYN_SMEM);

    wh_gemm_kernel <<<256, 256>>>(h, Wm, a);
    gat_main_kernel<<<GRID_MAIN, 512, DYN_SMEM>>>(adj, out);
}